// round 6
// baseline (speedup 1.0000x reference)
#include <cuda_runtime.h>
#include <cuda_bf16.h>
#include <cstdint>

// Problem constants
#define BB   8
#define CC   64
#define NN   4096
#define OO   128
#define KNN  20

#define RESP 132      // gathermax result tile pitch
#define APITCH 72     // bf16 smem tile pitch (144B: 16B-aligned, ldmatrix conflict-free)
#define SCRP 68       // score tile pitch (floats)

// single dynamic-smem symbol shared by all kernels
extern __shared__ char smem_dyn[];

// ---------------- scratch (static device globals; no allocation) -------------
__device__ float g_xx[BB * NN];                         // ||x_j||^2
__device__ float g_Ut[CC * 256];                        // combined weights [c][o']
__device__ float g_GT[(size_t)BB * NN * OO];            // G^T: [b][j][o]
__device__ float g_HT[(size_t)BB * NN * OO];            // H^T: [b][i][o]
__device__ int   g_idx[(size_t)BB * NN * KNN];          // knn indices
__device__ __nv_bfloat16 g_xt_hi[(size_t)BB * NN * CC]; // x^T split hi: [b][j][c]
__device__ __nv_bfloat16 g_xt_lo[(size_t)BB * NN * CC]; // x^T split lo: [b][j][c]

// ---------------- PTX helpers (base ISA only: ldmatrix + mma.sync) -----------
__device__ __forceinline__ uint32_t smem_u32(const void* p) {
    uint32_t a;
    asm("{ .reg .u64 t; cvta.to.shared.u64 t, %1; cvt.u32.u64 %0, t; }" : "=r"(a) : "l"(p));
    return a;
}
__device__ __forceinline__ void ldsm_x4(uint32_t* r, uint32_t addr) {
    asm volatile("ldmatrix.sync.aligned.m8n8.x4.shared.b16 {%0,%1,%2,%3}, [%4];"
                 : "=r"(r[0]), "=r"(r[1]), "=r"(r[2]), "=r"(r[3]) : "r"(addr));
}
__device__ __forceinline__ void mma16816(float* d, const uint32_t* a, const uint32_t* b) {
    asm volatile("mma.sync.aligned.m16n8k16.row.col.f32.bf16.bf16.f32 "
                 "{%0,%1,%2,%3}, {%4,%5,%6,%7}, {%8,%9}, {%0,%1,%2,%3};"
                 : "+f"(d[0]), "+f"(d[1]), "+f"(d[2]), "+f"(d[3])
                 : "r"(a[0]), "r"(a[1]), "r"(a[2]), "r"(a[3]), "r"(b[0]), "r"(b[1]));
}

// ---------------- kernel 1: transpose + bf16 split + xx ----------------------
__global__ __launch_bounds__(256) void split_kernel(const float* __restrict__ x) {
    __shared__ float tile[64 * 68];
    __shared__ float part[64 * 4];
    int b = blockIdx.y, jbase = blockIdx.x * 64, t = threadIdx.x;
    const float* xb = x + (size_t)b * CC * NN;
    for (int k = t; k < 64 * 16; k += 256) {
        int c = k >> 4, p = k & 15;
        *(float4*)&tile[c * 68 + p * 4] = *(const float4*)&xb[c * NN + jbase + p * 4];
    }
    __syncthreads();
    int jl = t >> 2, g = t & 3;
    __nv_bfloat16 hi[16], lo[16];
    float ss = 0.f;
#pragma unroll
    for (int cc = 0; cc < 16; ++cc) {
        float v = tile[(g * 16 + cc) * 68 + jl];
        ss += v * v;
        __nv_bfloat16 h = __float2bfloat16(v);
        hi[cc] = h;
        lo[cc] = __float2bfloat16(v - __bfloat162float(h));
    }
    part[jl * 4 + g] = ss;
    size_t base = ((size_t)b * NN + jbase + jl) * CC + g * 16;
    *(uint4*)&g_xt_hi[base]     = *(uint4*)&hi[0];
    *(uint4*)&g_xt_hi[base + 8] = *(uint4*)&hi[8];
    *(uint4*)&g_xt_lo[base]     = *(uint4*)&lo[0];
    *(uint4*)&g_xt_lo[base + 8] = *(uint4*)&lo[8];
    __syncthreads();
    if (t < 64)
        g_xx[b * NN + jbase + t] = part[t * 4] + part[t * 4 + 1] + part[t * 4 + 2] + part[t * 4 + 3];
}

// ---------------- kernel 2: build combined weight Ut[c][o'] ------------------
__global__ void uprep_kernel(const float* __restrict__ W) {
    int c = blockIdx.x;
    int o = threadIdx.x;
    float v;
    if (o < OO) v = W[o * (2 * CC) + c];
    else {
        int oo = o - OO;
        v = W[oo * (2 * CC) + CC + c] - W[oo * (2 * CC) + c];
    }
    g_Ut[c * 256 + o] = v;
}

// ---------------- kernel 3: GH^T GEMM -> g_GT / g_HT -------------------------
__global__ __launch_bounds__(256) void gemm_gh_kernel(const float* __restrict__ x,
                                                      const float* __restrict__ bvec) {
    float* sm = (float*)smem_dyn;
    float* su = sm;                 // [64][256]
    float* sx = sm + CC * 256;      // [64][64]

    int b = blockIdx.y;
    int jbase = blockIdx.x * 64;
    int t = threadIdx.x;
    int tx = t & 7;
    int ty = t >> 3;

    const float4* ut4 = (const float4*)g_Ut;
    float4* su4 = (float4*)su;
    for (int k = t; k < CC * 256 / 4; k += 256) su4[k] = ut4[k];

    const float* xb = x + (size_t)b * CC * NN;
    for (int k = t; k < CC * 16; k += 256) {
        int c = k >> 4, p = k & 15;
        *(float4*)&sx[c * 64 + p * 4] = *(const float4*)&xb[c * NN + jbase + p * 4];
    }
    __syncthreads();

    float acc[8][8];
#pragma unroll
    for (int i = 0; i < 8; ++i)
#pragma unroll
        for (int j = 0; j < 8; ++j) acc[i][j] = 0.f;

#pragma unroll 4
    for (int c = 0; c < CC; ++c) {
        float4 a0 = *(float4*)&su[c * 256 + ty * 8];
        float4 a1 = *(float4*)&su[c * 256 + ty * 8 + 4];
        float4 b0 = *(float4*)&sx[c * 64 + tx * 8];
        float4 b1 = *(float4*)&sx[c * 64 + tx * 8 + 4];
        float aa[8] = {a0.x, a0.y, a0.z, a0.w, a1.x, a1.y, a1.z, a1.w};
        float bb[8] = {b0.x, b0.y, b0.z, b0.w, b1.x, b1.y, b1.z, b1.w};
#pragma unroll
        for (int i = 0; i < 8; ++i)
#pragma unroll
            for (int j = 0; j < 8; ++j) acc[i][j] += aa[i] * bb[j];
    }

    int obase = ty * 8;
    bool isH = (obase >= OO);
    float bias[8];
    if (isH) {
#pragma unroll
        for (int i = 0; i < 8; ++i) bias[i] = bvec[obase - OO + i];
    }
#pragma unroll
    for (int jq = 0; jq < 8; ++jq) {
        int j = jbase + tx * 8 + jq;
        float* dst = isH ? &g_HT[((size_t)b * NN + j) * OO + (obase - OO)]
                         : &g_GT[((size_t)b * NN + j) * OO + obase];
#pragma unroll
        for (int i = 0; i < 8; ++i) {
            float v = acc[i][jq];
            if (isH) v += bias[i];
            dst[i] = v;
        }
    }
}

// ---------------- kernel 4: HMMA distance GEMM + streaming top-20 ------------
// 256 threads (8 warps). Warp w owns rows [16w, 16w+16). j streamed in 64-chunks.
// dot = Ahi.Bhi + Ahi.Blo + Alo.Bhi + Alo.Blo (exact-ish bf16 split, fp32 accum).
// smem offsets (bytes):
#define OFF_AHI  0
#define OFF_ALO  (OFF_AHI + 128 * APITCH * 2)   // 18432
#define OFF_BHI  (OFF_ALO + 128 * APITCH * 2)   // 36864
#define OFF_BLO  (OFF_BHI + 64 * APITCH * 2)    // 46080
#define OFF_SCR  (OFF_BLO + 64 * APITCH * 2)    // 55296
#define OFF_NXX  (OFF_SCR + 128 * SCRP * 4)     // 90112
#define OFF_LV   (OFF_NXX + 64 * 4)             // 90368
#define OFF_LI   (OFF_LV + 128 * KNN * 4)       // 100608
#define KNN_SMEM (OFF_LI + 128 * KNN * 4)       // 110848 bytes

__global__ __launch_bounds__(256, 2) void knn_kernel() {
    char* sm = smem_dyn;
    uint32_t sbase = smem_u32(sm);
    int t = threadIdx.x;
    int warp = t >> 5, lane = t & 31;
    int b = blockIdx.y;
    int ibase = blockIdx.x * 128;

    __nv_bfloat16* sAhi = (__nv_bfloat16*)(sm + OFF_AHI);
    __nv_bfloat16* sAlo = (__nv_bfloat16*)(sm + OFF_ALO);
    __nv_bfloat16* sBhi = (__nv_bfloat16*)(sm + OFF_BHI);
    __nv_bfloat16* sBlo = (__nv_bfloat16*)(sm + OFF_BLO);
    float* scr = (float*)(sm + OFF_SCR);
    float* nxx = (float*)(sm + OFF_NXX);
    float* lv  = (float*)(sm + OFF_LV);
    int*   li  = (int*)(sm + OFF_LI);

    // init top-k lists
    for (int k = t; k < 128 * KNN; k += 256) { lv[k] = -3.4e38f; li[k] = 0; }

    // load A tiles (hi/lo), pitch APITCH: 1024 16B-chunks per tile
    {
        const uint4* srcH = (const uint4*)(g_xt_hi + ((size_t)b * NN + ibase) * CC);
        const uint4* srcL = (const uint4*)(g_xt_lo + ((size_t)b * NN + ibase) * CC);
#pragma unroll
        for (int it = 0; it < 4; ++it) {
            int k = t + it * 256;          // row=k>>3, p=k&7
            int row = k >> 3, p = k & 7;
            *(uint4*)&sAhi[row * APITCH + p * 8] = srcH[k];
            *(uint4*)&sAlo[row * APITCH + p * 8] = srcL[k];
        }
    }

    const float* xxb = g_xx + b * NN;
    float thr = -3.4e38f;
    float* lvr = lv + t * KNN;
    int*   lir = li + t * KNN;
    int mrow0 = warp * 16;

    // ldmatrix lane address components
    int arow = (lane & 7) + 8 * ((lane >> 3) & 1);  // A: rows 0-15 pattern
    int asel = 8 * (lane >> 4);                     // A: k-half select
    int brow = ((lane >> 4) & 1) * 8 + (lane & 7);  // B pair: row within 16-row pair
    int bsel = 8 * ((lane >> 3) & 1);               // B: k-half select

    for (int jbase = 0; jbase < NN; jbase += 64) {
        // load B tiles (64 rows x 64 bf16, hi+lo): 512 chunks each
        const uint4* srcH = (const uint4*)(g_xt_hi + ((size_t)b * NN + jbase) * CC);
        const uint4* srcL = (const uint4*)(g_xt_lo + ((size_t)b * NN + jbase) * CC);
#pragma unroll
        for (int it = 0; it < 2; ++it) {
            int k = t + it * 256;
            int row = k >> 3, p = k & 7;
            *(uint4*)&sBhi[row * APITCH + p * 8] = srcH[k];
            *(uint4*)&sBlo[row * APITCH + p * 8] = srcL[k];
        }
        if (t < 16) {
            float4 v = *(const float4*)&xxb[jbase + t * 4];
            v.x = -v.x; v.y = -v.y; v.z = -v.z; v.w = -v.w;
            *(float4*)&nxx[t * 4] = v;
        }
        __syncthreads();   // B ready; also joins previous chunk's scan

        float acc[8][4];
#pragma unroll
        for (int nj = 0; nj < 8; ++nj)
#pragma unroll
            for (int q = 0; q < 4; ++q) acc[nj][q] = 0.f;

#pragma unroll
        for (int ks = 0; ks < 4; ++ks) {
            int kc = ks * 16;
            uint32_t ah[4], al[4], bh[8][2], bl[8][2];
            {
                uint32_t off = ((mrow0 + arow) * APITCH + kc + asel) * 2;
                ldsm_x4(ah, sbase + OFF_AHI + off);
                ldsm_x4(al, sbase + OFF_ALO + off);
            }
#pragma unroll
            for (int njp = 0; njp < 4; ++njp) {      // pairs of n-tiles via x4
                uint32_t off = ((njp * 16 + brow) * APITCH + kc + bsel) * 2;
                ldsm_x4(&bh[njp * 2][0], sbase + OFF_BHI + off);
                ldsm_x4(&bl[njp * 2][0], sbase + OFF_BLO + off);
            }
#pragma unroll
            for (int nj = 0; nj < 8; ++nj) {
                mma16816(acc[nj], ah, bh[nj]);
                mma16816(acc[nj], ah, bl[nj]);
                mma16816(acc[nj], al, bh[nj]);
                mma16816(acc[nj], al, bl[nj]);
            }
        }

        // write D fragments to scr: lane holds rows mrow0+gid, mrow0+8+gid
        int gid = lane >> 2, tig = lane & 3;
#pragma unroll
        for (int nj = 0; nj < 8; ++nj) {
            int jc = nj * 8 + tig * 2;
            *(float2*)&scr[(mrow0 + gid) * SCRP + jc]     = make_float2(acc[nj][0], acc[nj][1]);
            *(float2*)&scr[(mrow0 + 8 + gid) * SCRP + jc] = make_float2(acc[nj][2], acc[nj][3]);
        }
        __syncthreads();   // scores visible

        // streaming top-20: thread t (< 128) owns row t
        if (t < 128) {
            const float* srow = scr + t * SCRP;
#pragma unroll 4
            for (int jj = 0; jj < 64; jj += 4) {
                float4 d = *(const float4*)&srow[jj];
                float4 nx = *(const float4*)&nxx[jj];
                float vs[4];
                vs[0] = fmaf(2.f, d.x, nx.x);
                vs[1] = fmaf(2.f, d.y, nx.y);
                vs[2] = fmaf(2.f, d.z, nx.z);
                vs[3] = fmaf(2.f, d.w, nx.w);
#pragma unroll
                for (int q = 0; q < 4; ++q) {
                    float s = vs[q];
                    if (s > thr) {
                        int p = KNN - 1;
                        while (p > 0 && lvr[p - 1] < s) {
                            lvr[p] = lvr[p - 1];
                            lir[p] = lir[p - 1];
                            --p;
                        }
                        lvr[p] = s;
                        lir[p] = jbase + jj + q;
                        thr = lvr[KNN - 1];
                    }
                }
            }
        }
        __syncthreads();   // scan done before scr/B overwritten
    }

    if (t < 128) {
        int* dst = &g_idx[((size_t)b * NN + ibase + t) * KNN];
#pragma unroll
        for (int k = 0; k < KNN; ++k) dst[k] = lir[k];
    }
}

// ---------------- kernel 5: gather-max + leaky + transposed write ------------
__global__ __launch_bounds__(256) void gathermax_kernel(float* __restrict__ out) {
    __shared__ int   sidx[32 * KNN];
    __shared__ float sres[32 * RESP];
    int b = blockIdx.y;
    int ibase = blockIdx.x * 32;
    int t = threadIdx.x;
    int w = t >> 5;
    int l = t & 31;

    for (int k = t; k < 32 * KNN; k += 256)
        sidx[k] = g_idx[((size_t)b * NN + ibase) * KNN + k];
    __syncthreads();

    const float* GTb = g_GT + (size_t)b * NN * OO;
    const float* HTb = g_HT + (size_t)b * NN * OO;

#pragma unroll
    for (int p = 0; p < 4; ++p) {
        int pp = w * 4 + p;
        int i = ibase + pp;
        float4 m = make_float4(-3.4e38f, -3.4e38f, -3.4e38f, -3.4e38f);
#pragma unroll
        for (int k = 0; k < KNN; ++k) {
            int j = sidx[pp * KNN + k];
            float4 g = *(const float4*)&GTb[(size_t)j * OO + l * 4];
            m.x = fmaxf(m.x, g.x); m.y = fmaxf(m.y, g.y);
            m.z = fmaxf(m.z, g.z); m.w = fmaxf(m.w, g.w);
        }
        float4 h = *(const float4*)&HTb[(size_t)i * OO + l * 4];
        float v0 = m.x + h.x, v1 = m.y + h.y, v2 = m.z + h.z, v3 = m.w + h.w;
        v0 = v0 >= 0.f ? v0 : 0.2f * v0;
        v1 = v1 >= 0.f ? v1 : 0.2f * v1;
        v2 = v2 >= 0.f ? v2 : 0.2f * v2;
        v3 = v3 >= 0.f ? v3 : 0.2f * v3;
        *(float4*)&sres[pp * RESP + l * 4] = make_float4(v0, v1, v2, v3);
    }
    __syncthreads();

    float* ob = out + (size_t)b * OO * NN;
    for (int k = t; k < OO * 32; k += 256) {
        int o = k >> 5, ii = k & 31;
        ob[(size_t)o * NN + ibase + ii] = sres[ii * RESP + o];
    }
}

// ---------------- launch ------------------------------------------------------
extern "C" void kernel_launch(void* const* d_in, const int* in_sizes, int n_in,
                              void* d_out, int out_size) {
    const float* x    = (const float*)d_in[0];   // (8, 64, 4096)
    const float* W    = (const float*)d_in[1];   // (128, 128)
    const float* bvec = (const float*)d_in[2];   // (128,)
    float* out = (float*)d_out;                  // (8, 128, 4096)

    const int SMEM_GEMM = (CC * 256 + CC * 64) * 4;   // 80KB
    cudaFuncSetAttribute(gemm_gh_kernel, cudaFuncAttributeMaxDynamicSharedMemorySize, SMEM_GEMM);
    cudaFuncSetAttribute(knn_kernel,     cudaFuncAttributeMaxDynamicSharedMemorySize, KNN_SMEM);

    split_kernel<<<dim3(NN / 64, BB), 256>>>(x);
    uprep_kernel<<<CC, 256>>>(W);
    gemm_gh_kernel<<<dim3(NN / 64, BB), 256, SMEM_GEMM>>>(x, bvec);
    knn_kernel<<<dim3(NN / 128, BB), 256, KNN_SMEM>>>();
    gathermax_kernel<<<dim3(NN / 32, BB), 256>>>(out);
}

// round 8
// speedup vs baseline: 1.5194x; 1.5194x over previous
#include <cuda_runtime.h>
#include <cuda_bf16.h>
#include <cstdint>

// Problem constants
#define BB   8
#define CC   64
#define NN   4096
#define OO   128
#define KNN  20

#define RESP 132      // gathermax result tile pitch
#define AP   72       // bf16 smem tile pitch (144B; conflict-free ldmatrix)

// single dynamic-smem symbol shared by all kernels
extern __shared__ char smem_dyn[];

// ---------------- scratch (static device globals; no allocation) -------------
__device__ float g_xx[BB * NN];                         // ||x_j||^2
__device__ float g_Ut[CC * 256];                        // combined weights [c][o']
__device__ float g_GT[(size_t)BB * NN * OO];            // G^T: [b][j][o]
__device__ float g_HT[(size_t)BB * NN * OO];            // H^T: [b][i][o]
__device__ int   g_idx[(size_t)BB * NN * KNN];          // knn indices
__device__ __nv_bfloat16 g_xt_hi[(size_t)BB * NN * CC]; // x^T split hi: [b][j][c]
__device__ __nv_bfloat16 g_xt_lo[(size_t)BB * NN * CC]; // x^T split lo: [b][j][c]

// ---------------- PTX helpers (base ISA only: ldmatrix + mma.sync) -----------
__device__ __forceinline__ uint32_t smem_u32(const void* p) {
    uint32_t a;
    asm("{ .reg .u64 t; cvta.to.shared.u64 t, %1; cvt.u32.u64 %0, t; }" : "=r"(a) : "l"(p));
    return a;
}
__device__ __forceinline__ void ldsm_x4(uint32_t* r, uint32_t addr) {
    asm volatile("ldmatrix.sync.aligned.m8n8.x4.shared.b16 {%0,%1,%2,%3}, [%4];"
                 : "=r"(r[0]), "=r"(r[1]), "=r"(r[2]), "=r"(r[3]) : "r"(addr));
}
__device__ __forceinline__ void mma16816(float* d, const uint32_t* a, const uint32_t* b) {
    asm volatile("mma.sync.aligned.m16n8k16.row.col.f32.bf16.bf16.f32 "
                 "{%0,%1,%2,%3}, {%4,%5,%6,%7}, {%8,%9}, {%0,%1,%2,%3};"
                 : "+f"(d[0]), "+f"(d[1]), "+f"(d[2]), "+f"(d[3])
                 : "r"(a[0]), "r"(a[1]), "r"(a[2]), "r"(a[3]), "r"(b[0]), "r"(b[1]));
}

// sorted-desc register top-20 insert (caller guarantees s > v[19])
__device__ __forceinline__ void insert20(float s, int j, float (&v)[20], int (&ix)[20]) {
    bool c[20];
#pragma unroll
    for (int q = 0; q < 20; ++q) c[q] = s > v[q];
#pragma unroll
    for (int q = 19; q >= 1; --q) {
        if (c[q]) {
            v[q]  = c[q - 1] ? v[q - 1] : s;
            ix[q] = c[q - 1] ? ix[q - 1] : j;
        }
    }
    if (c[0]) { v[0] = s; ix[0] = j; }
}

// ---------------- kernel 1: transpose + bf16 split + xx ----------------------
__global__ __launch_bounds__(256) void split_kernel(const float* __restrict__ x) {
    __shared__ float tile[64 * 68];
    __shared__ float part[64 * 4];
    int b = blockIdx.y, jbase = blockIdx.x * 64, t = threadIdx.x;
    const float* xb = x + (size_t)b * CC * NN;
    for (int k = t; k < 64 * 16; k += 256) {
        int c = k >> 4, p = k & 15;
        *(float4*)&tile[c * 68 + p * 4] = *(const float4*)&xb[c * NN + jbase + p * 4];
    }
    __syncthreads();
    int jl = t >> 2, g = t & 3;
    __nv_bfloat16 hi[16], lo[16];
    float ss = 0.f;
#pragma unroll
    for (int cc = 0; cc < 16; ++cc) {
        float v = tile[(g * 16 + cc) * 68 + jl];
        ss += v * v;
        __nv_bfloat16 h = __float2bfloat16(v);
        hi[cc] = h;
        lo[cc] = __float2bfloat16(v - __bfloat162float(h));
    }
    part[jl * 4 + g] = ss;
    size_t base = ((size_t)b * NN + jbase + jl) * CC + g * 16;
    *(uint4*)&g_xt_hi[base]     = *(uint4*)&hi[0];
    *(uint4*)&g_xt_hi[base + 8] = *(uint4*)&hi[8];
    *(uint4*)&g_xt_lo[base]     = *(uint4*)&lo[0];
    *(uint4*)&g_xt_lo[base + 8] = *(uint4*)&lo[8];
    __syncthreads();
    if (t < 64)
        g_xx[b * NN + jbase + t] = part[t * 4] + part[t * 4 + 1] + part[t * 4 + 2] + part[t * 4 + 3];
}

// ---------------- kernel 2: build combined weight Ut[c][o'] ------------------
__global__ void uprep_kernel(const float* __restrict__ W) {
    int c = blockIdx.x;
    int o = threadIdx.x;
    float v;
    if (o < OO) v = W[o * (2 * CC) + c];
    else {
        int oo = o - OO;
        v = W[oo * (2 * CC) + CC + c] - W[oo * (2 * CC) + c];
    }
    g_Ut[c * 256 + o] = v;
}

// ---------------- kernel 3: GH^T GEMM -> g_GT / g_HT -------------------------
__global__ __launch_bounds__(256) void gemm_gh_kernel(const float* __restrict__ x,
                                                      const float* __restrict__ bvec) {
    float* sm = (float*)smem_dyn;
    float* su = sm;                 // [64][256]
    float* sx = sm + CC * 256;      // [64][64]

    int b = blockIdx.y;
    int jbase = blockIdx.x * 64;
    int t = threadIdx.x;
    int tx = t & 7;
    int ty = t >> 3;

    const float4* ut4 = (const float4*)g_Ut;
    float4* su4 = (float4*)su;
    for (int k = t; k < CC * 256 / 4; k += 256) su4[k] = ut4[k];

    const float* xb = x + (size_t)b * CC * NN;
    for (int k = t; k < CC * 16; k += 256) {
        int c = k >> 4, p = k & 15;
        *(float4*)&sx[c * 64 + p * 4] = *(const float4*)&xb[c * NN + jbase + p * 4];
    }
    __syncthreads();

    float acc[8][8];
#pragma unroll
    for (int i = 0; i < 8; ++i)
#pragma unroll
        for (int j = 0; j < 8; ++j) acc[i][j] = 0.f;

#pragma unroll 4
    for (int c = 0; c < CC; ++c) {
        float4 a0 = *(float4*)&su[c * 256 + ty * 8];
        float4 a1 = *(float4*)&su[c * 256 + ty * 8 + 4];
        float4 b0 = *(float4*)&sx[c * 64 + tx * 8];
        float4 b1 = *(float4*)&sx[c * 64 + tx * 8 + 4];
        float aa[8] = {a0.x, a0.y, a0.z, a0.w, a1.x, a1.y, a1.z, a1.w};
        float bb[8] = {b0.x, b0.y, b0.z, b0.w, b1.x, b1.y, b1.z, b1.w};
#pragma unroll
        for (int i = 0; i < 8; ++i)
#pragma unroll
            for (int j = 0; j < 8; ++j) acc[i][j] += aa[i] * bb[j];
    }

    int obase = ty * 8;
    bool isH = (obase >= OO);
    float bias[8];
    if (isH) {
#pragma unroll
        for (int i = 0; i < 8; ++i) bias[i] = bvec[obase - OO + i];
    }
#pragma unroll
    for (int jq = 0; jq < 8; ++jq) {
        int j = jbase + tx * 8 + jq;
        float* dst = isH ? &g_HT[((size_t)b * NN + j) * OO + (obase - OO)]
                         : &g_GT[((size_t)b * NN + j) * OO + obase];
#pragma unroll
        for (int i = 0; i < 8; ++i) {
            float v = acc[i][jq];
            if (isH) v += bias[i];
            dst[i] = v;
        }
    }
}

// ---------------- kernel 4: HMMA distance GEMM + register top-20 -------------
// 256 threads (8 warps). Warp w: rows [16w,16w+16). j in 64-chunks, B double-buf.
// K=64, 4-term bf16 split, EXACT fp32 xx subtraction at filter time.
#define A_TILE (128 * AP * 2)            // 18432 bytes per A sub-tile
#define B_TILE (64 * AP * 2)             // 9216 bytes per B sub-tile
#define OFF_AHI 0
#define OFF_ALO A_TILE                   // 18432
#define OFF_B   (2 * A_TILE)             // 36864
#define B_BUF_STRIDE (2 * B_TILE)        // 18432 (hi at +0, lo at +B_TILE)
#define OFF_NXX (OFF_B + 2 * B_BUF_STRIDE)    // 73728 (2 bufs x 64 floats)
#define KNN_SMEM (OFF_NXX + 2 * 64 * 4)       // 74240 bytes

__device__ __forceinline__ void load_b_tile(char* sm, int b, int jbase, int buf, int t) {
    __nv_bfloat16* bh = (__nv_bfloat16*)(sm + OFF_B + buf * B_BUF_STRIDE);
    __nv_bfloat16* bl = (__nv_bfloat16*)(sm + OFF_B + buf * B_BUF_STRIDE + B_TILE);
    const uint4* srcH = (const uint4*)(g_xt_hi + ((size_t)b * NN + jbase) * CC);
    const uint4* srcL = (const uint4*)(g_xt_lo + ((size_t)b * NN + jbase) * CC);
#pragma unroll
    for (int it = 0; it < 2; ++it) {
        int k = t + it * 256;
        int row = k >> 3, p = k & 7;
        *(uint4*)&bh[row * AP + p * 8] = srcH[k];
        *(uint4*)&bl[row * AP + p * 8] = srcL[k];
    }
    if (t >= 64 && t < 128) {
        int r = t - 64;
        ((float*)(sm + OFF_NXX))[buf * 64 + r] = -g_xx[b * NN + jbase + r];
    }
}

__global__ __launch_bounds__(256, 2) void knn_kernel() {
    char* sm = smem_dyn;
    uint32_t sbase = smem_u32(sm);
    int t = threadIdx.x;
    int warp = t >> 5, lane = t & 31;
    int gid = lane >> 2, tig = lane & 3;
    int b = blockIdx.y;
    int ibase = blockIdx.x * 128;
    int mrow0 = warp * 16;

    __nv_bfloat16* sAhi = (__nv_bfloat16*)(sm + OFF_AHI);
    __nv_bfloat16* sAlo = (__nv_bfloat16*)(sm + OFF_ALO);
    float* nxx = (float*)(sm + OFF_NXX);

    // A data
    {
        const uint4* srcH = (const uint4*)(g_xt_hi + ((size_t)b * NN + ibase) * CC);
        const uint4* srcL = (const uint4*)(g_xt_lo + ((size_t)b * NN + ibase) * CC);
#pragma unroll
        for (int it = 0; it < 4; ++it) {
            int k = t + it * 256;
            int row = k >> 3, p = k & 7;
            *(uint4*)&sAhi[row * AP + p * 8] = srcH[k];
            *(uint4*)&sAlo[row * AP + p * 8] = srcL[k];
        }
    }
    load_b_tile(sm, b, 0, 0, t);   // preload chunk 0

    // register top-20 (sorted desc) + local pending stack
    float v[20]; int ixr[20];
#pragma unroll
    for (int q = 0; q < 20; ++q) { v[q] = -3.4e38f; ixr[q] = 0; }
    float pend_s[40]; int pend_j[40]; int cnt = 0;

    // ldmatrix lane address components
    int arow = (lane & 7) + 8 * ((lane >> 3) & 1);
    int asel = 8 * (lane >> 4);
    int brow = ((lane >> 4) & 1) * 8 + (lane & 7);
    int bsel = 8 * ((lane >> 3) & 1);
    bool oddh = tig & 1;
    int colbase = 4 * (tig >> 1);

    for (int ch = 0; ch < 64; ++ch) {
        __syncthreads();   // B[ch]+nxx[ch] ready; all warps done with iter ch-1
        int curb = ch & 1;
        if (ch < 63) load_b_tile(sm, b, (ch + 1) * 64, curb ^ 1, t);

        float acc[8][4];
#pragma unroll
        for (int nj = 0; nj < 8; ++nj)
#pragma unroll
            for (int q = 0; q < 4; ++q) acc[nj][q] = 0.f;

#pragma unroll
        for (int ks = 0; ks < 4; ++ks) {
            int kc = ks * 16;
            uint32_t ah[4], al[4];
            uint32_t aoff = sbase + OFF_AHI + ((mrow0 + arow) * AP + kc + asel) * 2;
            ldsm_x4(ah, aoff);
            ldsm_x4(al, aoff + A_TILE);
#pragma unroll
            for (int njp = 0; njp < 4; ++njp) {
                uint32_t bh4[4], bl4[4];
                uint32_t boff = sbase + OFF_B + curb * B_BUF_STRIDE
                              + ((njp * 16 + brow) * AP + kc + bsel) * 2;
                ldsm_x4(bh4, boff);
                ldsm_x4(bl4, boff + B_TILE);
                mma16816(acc[njp * 2], ah, bh4);
                mma16816(acc[njp * 2], ah, bl4);
                mma16816(acc[njp * 2], al, bh4);
                mma16816(acc[njp * 2], al, bl4);
                mma16816(acc[njp * 2 + 1], ah, bh4 + 2);
                mma16816(acc[njp * 2 + 1], ah, bl4 + 2);
                mma16816(acc[njp * 2 + 1], al, bh4 + 2);
                mma16816(acc[njp * 2 + 1], al, bl4 + 2);
            }
        }

        // fragment swap -> lane owns ONE row, 4 consecutive cols per nj
        float thr = v[19];
        const float* nxc = nxx + curb * 64;
#pragma unroll
        for (int nj = 0; nj < 8; ++nj) {
            float d0 = acc[nj][0], d1 = acc[nj][1], d2 = acc[nj][2], d3 = acc[nj][3];
            float r0 = __shfl_xor_sync(0xffffffffu, oddh ? d0 : d2, 1);
            float r1 = __shfl_xor_sync(0xffffffffu, oddh ? d1 : d3, 1);
            float c0 = oddh ? r0 : d0;
            float c1 = oddh ? r1 : d1;
            float c2 = oddh ? d2 : r0;
            float c3 = oddh ? d3 : r1;
            int jc = nj * 8 + colbase;
            float4 nx = *(const float4*)&nxc[jc];
            float s0 = fmaf(2.f, c0, nx.x);
            float s1 = fmaf(2.f, c1, nx.y);
            float s2 = fmaf(2.f, c2, nx.z);
            float s3 = fmaf(2.f, c3, nx.w);
            int j0 = ch * 64 + jc;
            if (s0 > thr) { pend_s[cnt] = s0; pend_j[cnt] = j0;     ++cnt; }
            if (s1 > thr) { pend_s[cnt] = s1; pend_j[cnt] = j0 + 1; ++cnt; }
            if (s2 > thr) { pend_s[cnt] = s2; pend_j[cnt] = j0 + 2; ++cnt; }
            if (s3 > thr) { pend_s[cnt] = s3; pend_j[cnt] = j0 + 3; ++cnt; }
        }
        // batch drain (bounded: max 7 carried + 32 new < 40)
        if (cnt >= 8) {
            for (int u = 0; u < cnt; ++u) {
                float s = pend_s[u];
                if (s > v[19]) insert20(s, pend_j[u], v, ixr);
            }
            cnt = 0;
        }
    }
    // final drain
    for (int u = 0; u < cnt; ++u) {
        float s = pend_s[u];
        if (s > v[19]) insert20(s, pend_j[u], v, ixr);
    }

    __syncthreads();   // all MMA reads done -> overlay A (stv) and B (sti) regions
    {
        float* stv = (float*)sm;               // [128][43] floats (22016 B in A region)
        int*   sti = (int*)(sm + OFF_B);       // [128][43] ints  (22016 B in B region)
        int rloc = mrow0 + gid + 8 * (tig & 1);
        int half = tig >> 1;
        int base = rloc * 43 + half * 21;
#pragma unroll
        for (int q = 0; q < 20; ++q) { stv[base + q] = v[q]; sti[base + q] = ixr[q]; }
        stv[base + 20] = -3.4e38f;             // sentinel at 20 / 41
        __syncthreads();

        if (t < 128) {
            const float* a = stv + t * 43;
            const int*  ai = sti + t * 43;
            int ia = 0, ib = 21;
            int* dst = &g_idx[((size_t)b * NN + ibase + t) * KNN];
#pragma unroll
            for (int k = 0; k < KNN; ++k) {
                float va = a[ia], vb = a[ib];
                bool ta = va >= vb;
                dst[k] = ta ? ai[ia] : ai[ib];
                ia += ta;
                ib += !ta;
            }
        }
    }
}

// ---------------- kernel 5: gather-max + leaky + transposed write ------------
__global__ __launch_bounds__(256) void gathermax_kernel(float* __restrict__ out) {
    __shared__ int   sidx[32 * KNN];
    __shared__ float sres[32 * RESP];
    int b = blockIdx.y;
    int ibase = blockIdx.x * 32;
    int t = threadIdx.x;
    int w = t >> 5;
    int l = t & 31;

    for (int k = t; k < 32 * KNN; k += 256)
        sidx[k] = g_idx[((size_t)b * NN + ibase) * KNN + k];
    __syncthreads();

    const float* GTb = g_GT + (size_t)b * NN * OO;
    const float* HTb = g_HT + (size_t)b * NN * OO;

#pragma unroll
    for (int p = 0; p < 4; ++p) {
        int pp = w * 4 + p;
        int i = ibase + pp;
        float4 m = make_float4(-3.4e38f, -3.4e38f, -3.4e38f, -3.4e38f);
#pragma unroll
        for (int k = 0; k < KNN; ++k) {
            int j = sidx[pp * KNN + k];
            float4 g = *(const float4*)&GTb[(size_t)j * OO + l * 4];
            m.x = fmaxf(m.x, g.x); m.y = fmaxf(m.y, g.y);
            m.z = fmaxf(m.z, g.z); m.w = fmaxf(m.w, g.w);
        }
        float4 h = *(const float4*)&HTb[(size_t)i * OO + l * 4];
        float v0 = m.x + h.x, v1 = m.y + h.y, v2 = m.z + h.z, v3 = m.w + h.w;
        v0 = v0 >= 0.f ? v0 : 0.2f * v0;
        v1 = v1 >= 0.f ? v1 : 0.2f * v1;
        v2 = v2 >= 0.f ? v2 : 0.2f * v2;
        v3 = v3 >= 0.f ? v3 : 0.2f * v3;
        *(float4*)&sres[pp * RESP + l * 4] = make_float4(v0, v1, v2, v3);
    }
    __syncthreads();

    float* ob = out + (size_t)b * OO * NN;
    for (int k = t; k < OO * 32; k += 256) {
        int o = k >> 5, ii = k & 31;
        ob[(size_t)o * NN + ibase + ii] = sres[ii * RESP + o];
    }
}

// ---------------- launch ------------------------------------------------------
extern "C" void kernel_launch(void* const* d_in, const int* in_sizes, int n_in,
                              void* d_out, int out_size) {
    const float* x    = (const float*)d_in[0];   // (8, 64, 4096)
    const float* W    = (const float*)d_in[1];   // (128, 128)
    const float* bvec = (const float*)d_in[2];   // (128,)
    float* out = (float*)d_out;                  // (8, 128, 4096)

    const int SMEM_GEMM = (CC * 256 + CC * 64) * 4;   // 80KB
    cudaFuncSetAttribute(gemm_gh_kernel, cudaFuncAttributeMaxDynamicSharedMemorySize, SMEM_GEMM);
    cudaFuncSetAttribute(knn_kernel,     cudaFuncAttributeMaxDynamicSharedMemorySize, KNN_SMEM);

    split_kernel<<<dim3(NN / 64, BB), 256>>>(x);
    uprep_kernel<<<CC, 256>>>(W);
    gemm_gh_kernel<<<dim3(NN / 64, BB), 256, SMEM_GEMM>>>(x, bvec);
    knn_kernel<<<dim3(NN / 128, BB), 256, KNN_SMEM>>>();
    gathermax_kernel<<<dim3(NN / 32, BB), 256>>>(out);
}